// round 17
// baseline (speedup 1.0000x reference)
#include <cuda_runtime.h>
#include <cuda_fp16.h>
#include <math.h>
#include <stdint.h>

// ---------------------------------------------------------------------------
// Problem constants
// ---------------------------------------------------------------------------
#define Bsz   8
#define Himg  128
#define Wimg  128
#define Cdim  192
#define HID   768
#define WS    8
#define SHIFT 4
#define NH    6
#define HD    32
#define NTOK  (Bsz*Himg*Wimg)             // 131072
#define NWIN  2048
#define NPW   64

// ---------------------------------------------------------------------------
// Scratch
// ---------------------------------------------------------------------------
__device__ __align__(16) __half g_qkv[(size_t)NTOK * 3 * Cdim];
__device__ __align__(16) __half g_att[(size_t)NTOK * Cdim];
__device__ __align__(16) __half g_ln2[(size_t)NTOK * Cdim];
__device__ __align__(16) __half g_hh [(size_t)NTOK * HID];
__device__ __align__(16) float  g_x1 [(size_t)NTOK * Cdim];
__device__ __align__(16) __half g_wh[442368];   // qkv@0 proj@110592 fc1@147456 fc2@294912

// ---------------------------------------------------------------------------
// Helpers
// ---------------------------------------------------------------------------
__device__ __forceinline__ uint32_t smem_u32(const void* p) {
    uint32_t a;
    asm("{ .reg .u64 t; cvta.to.shared.u64 t, %1; cvt.u32.u64 %0, t; }" : "=r"(a) : "l"(p));
    return a;
}
__device__ __forceinline__ void cp_async16(uint32_t dst, const void* src) {
    asm volatile("cp.async.cg.shared.global [%0], [%1], 16;" :: "r"(dst), "l"(src) : "memory");
}
__device__ __forceinline__ void sts32(uint32_t addr, uint32_t v) {
    asm volatile("st.shared.b32 [%0], %1;" :: "r"(addr), "r"(v) : "memory");
}
__device__ __forceinline__ void ldsm4(uint32_t* r, uint32_t addr) {
    asm volatile("ldmatrix.sync.aligned.m8n8.x4.shared.b16 {%0,%1,%2,%3}, [%4];"
        : "=r"(r[0]), "=r"(r[1]), "=r"(r[2]), "=r"(r[3]) : "r"(addr));
}
__device__ __forceinline__ void ldsm4t(uint32_t* r, uint32_t addr) {
    asm volatile("ldmatrix.sync.aligned.m8n8.x4.trans.shared.b16 {%0,%1,%2,%3}, [%4];"
        : "=r"(r[0]), "=r"(r[1]), "=r"(r[2]), "=r"(r[3]) : "r"(addr));
}
__device__ __forceinline__ void mma16(float* c, const uint32_t* a, const uint32_t* b) {
    asm volatile("mma.sync.aligned.m16n8k16.row.col.f32.f16.f16.f32 "
        "{%0,%1,%2,%3}, {%4,%5,%6,%7}, {%8,%9}, {%0,%1,%2,%3};"
        : "+f"(c[0]), "+f"(c[1]), "+f"(c[2]), "+f"(c[3])
        : "r"(a[0]), "r"(a[1]), "r"(a[2]), "r"(a[3]), "r"(b[0]), "r"(b[1]));
}
__device__ __forceinline__ long win2orig(long t) {
    const int b_ = (int)(t >> 6), n = (int)(t & 63);
    const int b = b_ >> 8, wi = b_ & 255;
    const int h = ((wi >> 4) * 8 + (n >> 3) + SHIFT) & 127;
    const int w = ((wi & 15) * 8 + (n & 7) + SHIFT) & 127;
    return ((long)b * 128 + h) * 128 + w;
}
// Branchless GELU: Abramowitz-Stegun 7.1.26 erf approx (|err| < 1.5e-7)
__device__ __forceinline__ float gelu1(float x) {
    const float z  = 0.7071067811865475f * x;
    const float az = fabsf(z);
    const float t  = __fdividef(1.f, 1.f + 0.3275911f * az);
    float p = 1.061405429f;
    p = p * t - 1.453152027f;
    p = p * t + 1.421413741f;
    p = p * t - 0.284496736f;
    p = p * t + 0.254829592f;
    p = p * t;
    const float e  = __expf(-z * z);
    float er = 1.f - p * e;
    er = copysignf(er, z);
    return 0.5f * x * (1.f + er);
}

#define ACH 8192       // 64 rows x 128B
#define BCH 24576      // 192 rows x 128B
#define NTH 256

// 8 warps: 2m x 4n, warp tile 32x48, M-tile 64
#define DECOMP() \
    const int tid  = threadIdx.x; \
    const int wid  = tid >> 5; \
    const int lane = tid & 31; \
    const int g    = lane >> 2; \
    const int tig  = lane & 3; \
    const int m0w  = (wid >> 2) * 32; \
    const int n0w  = (wid & 3) * 48;

#define LDSM_SETUP() \
    const int l8 = lane & 7; \
    const int aHi = lane >> 4; \
    const uint32_t aOff0 = (uint32_t)(m0w + l8 + ((lane >> 3) & 1) * 8) * 128; \
    const int bHi = (lane >> 3) & 1; \
    const uint32_t bOff0 = (uint32_t)(n0w + l8 + ((lane >> 4) & 1) * 8) * 128;

#define KCHUNK_MMA(aB, bB) \
    _Pragma("unroll") \
    for (int s = 0; s < 4; s++) { \
        const uint32_t ac = (uint32_t)(((2 * s + aHi) ^ l8) << 4); \
        const uint32_t bc = (uint32_t)(((2 * s + bHi) ^ l8) << 4); \
        uint32_t af[2][4], bp[3][4]; \
        _Pragma("unroll") \
        for (int mi = 0; mi < 2; mi++) ldsm4(af[mi], (aB) + aOff0 + mi * 2048 + ac); \
        _Pragma("unroll") \
        for (int p = 0; p < 3; p++)  ldsm4(bp[p], (bB) + bOff0 + p * 2048 + bc); \
        _Pragma("unroll") \
        for (int mi = 0; mi < 2; mi++) \
            _Pragma("unroll") \
            for (int ni = 0; ni < 6; ni++) \
                mma16(acc[mi][ni], af[mi], &bp[ni >> 1][(ni & 1) * 2]); \
    }

#define CLEAR_ACC() \
    _Pragma("unroll") \
    for (int mi = 0; mi < 2; mi++) \
        _Pragma("unroll") \
        for (int ni = 0; ni < 6; ni++) \
            _Pragma("unroll") \
            for (int c = 0; c < 4; c++) acc[mi][ni][c] = 0.f;

// B chunk loader: 192 rows, 256 threads -> 6 iterations of 32 rows. buf in {0,1,2}
#define ISSUE_B(buf, nt, c) do { \
        const uint32_t bd = bBase + (uint32_t)(buf) * BCH + (uint32_t)lm * 128 + bswz; \
        const __half* sb_ = B + ((long)(nt) * 192 + lm) * Cdim + (c) * 64 + lq * 8; \
        _Pragma("unroll") \
        for (int it = 0; it < 6; it++) \
            cp_async16(bd + it * 4096, sb_ + (long)it * 32 * Cdim); \
        asm volatile("cp.async.commit_group;" ::: "memory"); \
    } while (0)

#define WAITG(ci, total) do { \
        if ((ci) == (total) - 1) asm volatile("cp.async.wait_group 0;" ::: "memory"); \
        else                     asm volatile("cp.async.wait_group 1;" ::: "memory"); \
    } while (0)

// ---------------------------------------------------------------------------
// Fused LN + GEMM (QKV): M-tile 64; A = LN(gather(x)) resident (3 chunks)
// ---------------------------------------------------------------------------
#define LN_SMEM (3*ACH + 3*BCH + 128)

__global__ void __launch_bounds__(NTH, 2)
gemm_ln(const float* __restrict__ Asrc, const __half* __restrict__ B,
        const float* __restrict__ bias, const float* __restrict__ gamma,
        const float* __restrict__ beta, __half* __restrict__ C, int N)
{
    extern __shared__ char dsm[];
    const uint32_t base  = (smem_u32(dsm) + 127u) & ~127u;
    const uint32_t bBase = base + 3 * ACH;

    DECOMP();
    LDSM_SETUP();
    const long m0 = (long)blockIdx.x * 64;
    const int lm = tid >> 3;
    const int lq = tid & 7;
    const uint32_t bswz = (uint32_t)((lq ^ (lm & 7)) << 4);
    const int NT = N / 192;
    const int total = NT * 3;

    ISSUE_B(0, 0, 0);
    ISSUE_B(1, 0, 1);

    // LN prologue: 8 warps x 8 rows = 64 rows
#pragma unroll 1
    for (int rr = 0; rr < 8; rr++) {
        const int row = wid * 8 + rr;
        const long t = m0 + row;
        const float* src = Asrc + win2orig(t) * Cdim;
        float2 v[3];
        float s = 0.f, ss = 0.f;
#pragma unroll
        for (int i = 0; i < 3; i++) {
            v[i] = *(const float2*)(src + 2 * lane + 64 * i);
            s  += v[i].x + v[i].y;
            ss += v[i].x * v[i].x + v[i].y * v[i].y;
        }
#pragma unroll
        for (int o = 16; o > 0; o >>= 1) {
            s  += __shfl_xor_sync(0xffffffffu, s,  o);
            ss += __shfl_xor_sync(0xffffffffu, ss, o);
        }
        const float mu  = s * (1.f / Cdim);
        const float var = ss * (1.f / Cdim) - mu * mu;
        const float r   = rsqrtf(var + 1e-5f);
        const uint32_t rowaddr = base + (uint32_t)row * 128 +
            ((((uint32_t)lane >> 2) ^ ((uint32_t)row & 7)) << 4) + ((uint32_t)lane & 3) * 4;
#pragma unroll
        for (int i = 0; i < 3; i++) {
            const int c = 2 * lane + 64 * i;
            const float2 gm = *(const float2*)(gamma + c);
            const float2 bt = *(const float2*)(beta + c);
            const __half2 hv = __floats2half2_rn((v[i].x - mu) * r * gm.x + bt.x,
                                                 (v[i].y - mu) * r * gm.y + bt.y);
            sts32(rowaddr + (uint32_t)i * ACH, *(const uint32_t*)&hv);
        }
    }

    float acc[2][6][4];
    CLEAR_ACC();

    for (int ci = 0; ci < total; ci++) {
        const int c = ci % 3;
        WAITG(ci, total);
        __syncthreads();
        if (ci + 2 < total) {
            const int cn = ci + 2;
            ISSUE_B(cn % 3, cn / 3, cn % 3);
        }

        KCHUNK_MMA(base + (uint32_t)c * ACH, bBase + (uint32_t)(ci % 3) * BCH);

        if (c == 2) {
            const int nt = ci / 3;
#pragma unroll
            for (int mi = 0; mi < 2; mi++) {
                const long r0 = m0 + m0w + mi * 16 + g;
                const long r1 = r0 + 8;
#pragma unroll
                for (int ni = 0; ni < 6; ni++) {
                    const int col = nt * 192 + n0w + ni * 8 + 2 * tig;
                    const float b0 = bias[col], b1 = bias[col + 1];
                    *(__half2*)(C + r0 * N + col) =
                        __floats2half2_rn(acc[mi][ni][0] + b0, acc[mi][ni][1] + b1);
                    *(__half2*)(C + r1 * N + col) =
                        __floats2half2_rn(acc[mi][ni][2] + b0, acc[mi][ni][3] + b1);
                    acc[mi][ni][0] = 0.f; acc[mi][ni][1] = 0.f;
                    acc[mi][ni][2] = 0.f; acc[mi][ni][3] = 0.f;
                }
            }
        }
    }
}

// ---------------------------------------------------------------------------
// A-resident fp16 GEMM (FC1): M-tile 64; C = GELU(A @ B^T + bias), half out
// ---------------------------------------------------------------------------
#define HA_SMEM (3*ACH + 3*BCH + 128)

__global__ void __launch_bounds__(NTH, 2)
gemm_ha(const __half* __restrict__ A, const __half* __restrict__ B,
        const float* __restrict__ bias, __half* __restrict__ C, int N)
{
    extern __shared__ char dsm[];
    const uint32_t base  = (smem_u32(dsm) + 127u) & ~127u;
    const uint32_t bBase = base + 3 * ACH;

    DECOMP();
    LDSM_SETUP();
    const long m0 = (long)blockIdx.x * 64;
    const int lm = tid >> 3;
    const int lq = tid & 7;
    const uint32_t bswz = (uint32_t)((lq ^ (lm & 7)) << 4);
    const int NT = N / 192;
    const int total = NT * 3;

    {
        const uint32_t da = base + (uint32_t)lm * 128 + bswz;
        const __half* sa = A + (m0 + lm) * Cdim + lq * 8;
#pragma unroll
        for (int c = 0; c < 3; c++)
#pragma unroll
            for (int it = 0; it < 2; it++)
                cp_async16(da + (uint32_t)c * ACH + it * 4096,
                           sa + (long)it * 32 * Cdim + c * 64);
        asm volatile("cp.async.commit_group;" ::: "memory");
    }

    ISSUE_B(0, 0, 0);
    ISSUE_B(1, 0, 1);

    float acc[2][6][4];
    CLEAR_ACC();

    for (int ci = 0; ci < total; ci++) {
        const int c = ci % 3;
        WAITG(ci, total);
        __syncthreads();
        if (ci + 2 < total) {
            const int cn = ci + 2;
            ISSUE_B(cn % 3, cn / 3, cn % 3);
        }

        KCHUNK_MMA(base + (uint32_t)c * ACH, bBase + (uint32_t)(ci % 3) * BCH);

        if (c == 2) {
            const int nt = ci / 3;
#pragma unroll
            for (int mi = 0; mi < 2; mi++) {
                const long r0 = m0 + m0w + mi * 16 + g;
                const long r1 = r0 + 8;
#pragma unroll
                for (int ni = 0; ni < 6; ni++) {
                    const int col = nt * 192 + n0w + ni * 8 + 2 * tig;
                    const float b0 = bias[col], b1 = bias[col + 1];
                    const float v0 = gelu1(acc[mi][ni][0] + b0);
                    const float v1 = gelu1(acc[mi][ni][1] + b1);
                    const float v2 = gelu1(acc[mi][ni][2] + b0);
                    const float v3 = gelu1(acc[mi][ni][3] + b1);
                    *(__half2*)(C + r0 * N + col) = __floats2half2_rn(v0, v1);
                    *(__half2*)(C + r1 * N + col) = __floats2half2_rn(v2, v3);
                    acc[mi][ni][0] = 0.f; acc[mi][ni][1] = 0.f;
                    acc[mi][ni][2] = 0.f; acc[mi][ni][3] = 0.f;
                }
            }
        }
    }
}

// ---------------------------------------------------------------------------
// Streaming fp16 GEMM, M-tile 64, triple-buffered. Paired-lane 16B epilogue IO.
// EPI=2: FC2 (+x1 res -> out fp32). EPI=3: proj (unshift + x res -> x1, LN2 -> ln2)
// ---------------------------------------------------------------------------
#define STAGE  (ACH + BCH)
#define GEMM_SMEM (3*STAGE + 128)

template <int EPI>
__global__ void __launch_bounds__(NTH, 2)
gemm_h(const __half* __restrict__ A, const __half* __restrict__ Bw,
       const float* __restrict__ bias, const float* __restrict__ res,
       float* __restrict__ C, __half* __restrict__ C2,
       const float* __restrict__ gamma, const float* __restrict__ beta,
       int N, int K)
{
    extern __shared__ char dsm[];
    const uint32_t base = (smem_u32(dsm) + 127u) & ~127u;

    DECOMP();
    LDSM_SETUP();
    const long m0 = (long)blockIdx.x * 64;

    const int lm = tid >> 3;
    const int lq = tid & 7;
    const __half* srcA = A + (m0 + lm) * K + lq * 8;
    const __half* srcB = Bw + (long)lm * K + lq * 8;
    const uint32_t swz = (uint32_t)((lq ^ (lm & 7)) << 4);
    const uint32_t dstA0 = base + (uint32_t)lm * 128 + swz;
    const uint32_t dstB0 = base + ACH + (uint32_t)lm * 128 + swz;

    float acc[2][6][4];
    CLEAR_ACC();

    const int NC = K >> 6;

#define ISSUE(buf, kc_) do { \
        const uint32_t so = (uint32_t)(buf) * STAGE; \
        const __half* sa = srcA + (kc_); \
        const __half* sb_ = srcB + (kc_); \
        _Pragma("unroll") \
        for (int it = 0; it < 2; it++) \
            cp_async16(dstA0 + so + it * 4096, sa + (long)it * 32 * K); \
        _Pragma("unroll") \
        for (int it = 0; it < 6; it++) \
            cp_async16(dstB0 + so + it * 4096, sb_ + (long)it * 32 * K); \
        asm volatile("cp.async.commit_group;" ::: "memory"); \
    } while (0)

    ISSUE(0, 0);
    if (NC > 1) ISSUE(1, 64);

    for (int i = 0; i < NC; i++) {
        WAITG(i, NC);
        __syncthreads();
        if (i + 2 < NC) ISSUE((i + 2) % 3, (i + 2) << 6);

        const uint32_t so = (uint32_t)(i % 3) * STAGE;
        KCHUNK_MMA(base + so, base + ACH + so);
    }
#undef ISSUE

    const bool evenT = ((tig & 1) == 0);

    // bias + residual into acc (paired float4 residual loads)
#pragma unroll
    for (int mi = 0; mi < 2; mi++) {
        const long rw0 = m0 + m0w + mi * 16 + g;
        const long r0 = (EPI == 3) ? win2orig(rw0) : rw0;
        const long r1 = (EPI == 3) ? win2orig(rw0 + 8) : (rw0 + 8);
        const long rL = evenT ? r0 : r1;
#pragma unroll
        for (int ni = 0; ni < 6; ni++) {
            const int col  = n0w + ni * 8 + 2 * tig;
            const int col4 = n0w + ni * 8 + (tig & 2) * 2;
            const float b0 = bias[col], b1 = bias[col + 1];
            const float4 rv = *(const float4*)(res + rL * N + col4);
            const float ox = __shfl_xor_sync(0xffffffffu, rv.x, 1);
            const float oy = __shfl_xor_sync(0xffffffffu, rv.y, 1);
            const float oz = __shfl_xor_sync(0xffffffffu, rv.z, 1);
            const float ow = __shfl_xor_sync(0xffffffffu, rv.w, 1);
            float r0a, r0b, r1a, r1b;
            if (evenT) { r0a = rv.x; r0b = rv.y; r1a = ox; r1b = oy; }
            else       { r0a = oz;   r0b = ow;   r1a = rv.z; r1b = rv.w; }
            acc[mi][ni][0] += b0 + r0a;
            acc[mi][ni][1] += b1 + r0b;
            acc[mi][ni][2] += b0 + r1a;
            acc[mi][ni][3] += b1 + r1b;
        }
    }

    if (EPI == 3) {
        float* rsum   = (float*)(dsm);
        float* rsumsq = rsum + 64;
        __syncthreads();
        if (tid < 64) { rsum[tid] = 0.f; rsumsq[tid] = 0.f; }
        __syncthreads();
#pragma unroll
        for (int mi = 0; mi < 2; mi++) {
            const int row0 = m0w + mi * 16 + g;
            float s0 = 0.f, q0 = 0.f, s1 = 0.f, q1 = 0.f;
#pragma unroll
            for (int ni = 0; ni < 6; ni++) {
                s0 += acc[mi][ni][0] + acc[mi][ni][1];
                q0 += acc[mi][ni][0] * acc[mi][ni][0] + acc[mi][ni][1] * acc[mi][ni][1];
                s1 += acc[mi][ni][2] + acc[mi][ni][3];
                q1 += acc[mi][ni][2] * acc[mi][ni][2] + acc[mi][ni][3] * acc[mi][ni][3];
            }
            atomicAdd(&rsum[row0], s0);     atomicAdd(&rsumsq[row0], q0);
            atomicAdd(&rsum[row0 + 8], s1); atomicAdd(&rsumsq[row0 + 8], q1);
        }
        __syncthreads();
    }

#pragma unroll
    for (int mi = 0; mi < 2; mi++) {
        const long rw0 = m0 + m0w + mi * 16 + g;
        const long r0 = (EPI == 3) ? win2orig(rw0) : rw0;
        const long r1 = (EPI == 3) ? win2orig(rw0 + 8) : (rw0 + 8);

        float mu0 = 0.f, rs0 = 0.f, mu1 = 0.f, rs1 = 0.f;
        if (EPI == 3) {
            const float* rsum   = (const float*)(dsm);
            const float* rsumsq = rsum + 64;
            const int row0 = m0w + mi * 16 + g;
            mu0 = rsum[row0] * (1.f / Cdim);
            rs0 = rsqrtf(rsumsq[row0] * (1.f / Cdim) - mu0 * mu0 + 1e-5f);
            mu1 = rsum[row0 + 8] * (1.f / Cdim);
            rs1 = rsqrtf(rsumsq[row0 + 8] * (1.f / Cdim) - mu1 * mu1 + 1e-5f);
        }
#pragma unroll
        for (int ni = 0; ni < 6; ni++) {
            const int col  = n0w + ni * 8 + 2 * tig;
            const int col4 = n0w + ni * 8 + (tig & 2) * 2;
            const float v0 = acc[mi][ni][0], v1 = acc[mi][ni][1];
            const float v2 = acc[mi][ni][2], v3 = acc[mi][ni][3];
            // paired float4 store of C (x1 / out)
            const float p0 = __shfl_xor_sync(0xffffffffu, v0, 1);
            const float p1 = __shfl_xor_sync(0xffffffffu, v1, 1);
            const float p2 = __shfl_xor_sync(0xffffffffu, v2, 1);
            const float p3 = __shfl_xor_sync(0xffffffffu, v3, 1);
            if (evenT) *(float4*)(C + r0 * N + col4) = make_float4(v0, v1, p0, p1);
            else       *(float4*)(C + r1 * N + col4) = make_float4(p2, p3, v2, v3);
            if (EPI == 3) {
                const float2 gm = *(const float2*)(gamma + col);
                const float2 bt = *(const float2*)(beta + col);
                const __half2 h0 = __floats2half2_rn(
                    (v0 - mu0) * rs0 * gm.x + bt.x, (v1 - mu0) * rs0 * gm.y + bt.y);
                const __half2 h1 = __floats2half2_rn(
                    (v2 - mu1) * rs1 * gm.x + bt.x, (v3 - mu1) * rs1 * gm.y + bt.y);
                const uint32_t u0 = *(const uint32_t*)&h0;
                const uint32_t u1 = *(const uint32_t*)&h1;
                const uint32_t q0 = __shfl_xor_sync(0xffffffffu, u0, 1);
                const uint32_t q1 = __shfl_xor_sync(0xffffffffu, u1, 1);
                if (evenT) { uint2 t2; t2.x = u0; t2.y = q0; *(uint2*)(C2 + r0 * N + col4) = t2; }
                else       { uint2 t2; t2.x = q1; t2.y = u1; *(uint2*)(C2 + r1 * N + col4) = t2; }
            }
        }
    }
}

// ---------------------------------------------------------------------------
// One-shot weight conversion fp32 -> fp16 (4 tensors)
// ---------------------------------------------------------------------------
__global__ void tohalf_all(const float* __restrict__ s0, const float* __restrict__ s1,
                           const float* __restrict__ s2, const float* __restrict__ s3,
                           __half* __restrict__ dst)
{
    const int i = blockIdx.x * 1024 + threadIdx.x * 4;
    const float* src;
    int off;
    if (i < 110592)      { src = s0; off = 0; }
    else if (i < 147456) { src = s1; off = 110592; }
    else if (i < 294912) { src = s2; off = 147456; }
    else                 { src = s3; off = 294912; }
    const float4 v = *(const float4*)(src + (i - off));
    __half2* d = (__half2*)(dst + i);
    d[0] = __floats2half2_rn(v.x, v.y);
    d[1] = __floats2half2_rn(v.z, v.w);
}

// ---------------------------------------------------------------------------
// Fused window attention v4: mma.sync. Block=(window, head), 64 threads (2 warps).
// ---------------------------------------------------------------------------
__global__ void __launch_bounds__(64, 8)
attn_kernel(const __half* __restrict__ qkv,
            const float* __restrict__ rpb,
            __half* __restrict__ out)
{
    const int win  = blockIdx.x;
    const int head = blockIdx.y;
    const int tid  = threadIdx.x;
    const int w    = tid >> 5;
    const int lane = tid & 31;
    const int g    = lane >> 2;
    const int tig  = lane & 3;

    __shared__ __half qs[64 * 40];   // 80B rows
    __shared__ __half ks[64 * 40];
    __shared__ __half vs[64 * 40];
    __shared__ float  sbias[225];
    __shared__ int    lab[64];

    const __half* base = qkv + (long)win * NPW * 576;
    {
        const uint4* qg = (const uint4*)(base + tid * 576 + head * HD);
        const uint4* kg = (const uint4*)(base + tid * 576 + 192 + head * HD);
        const uint4* vg = (const uint4*)(base + tid * 576 + 384 + head * HD);
        uint4* qd = (uint4*)(qs + tid * 40);
        uint4* kd = (uint4*)(ks + tid * 40);
        uint4* vd = (uint4*)(vs + tid * 40);
#pragma unroll
        for (int t = 0; t < 4; t++) { qd[t] = qg[t]; kd[t] = kg[t]; vd[t] = vg[t]; }
    }
    for (int idx = tid; idx < 225; idx += 64) sbias[idx] = rpb[idx * NH + head];
    {
        const int wi = win & 255;
        const int gh = (wi >> 4) * 8 + (tid >> 3);
        const int gw = (wi & 15) * 8 + (tid & 7);
        const int rh = (gh < Himg - WS) ? 0 : ((gh < Himg - SHIFT) ? 1 : 2);
        const int rw = (gw < Wimg - WS) ? 0 : ((gw < Wimg - SHIFT) ? 1 : 2);
        lab[tid] = rh * 3 + rw;
    }
    __syncthreads();

    const uint32_t qsb = smem_u32(qs);
    const uint32_t ksb = smem_u32(ks);
    const uint32_t vsb = smem_u32(vs);
    const int l7 = lane & 7;
    const uint32_t aRow = (uint32_t)(l7 + ((lane >> 3) & 1) * 8) * 80 + ((lane >> 4) & 1) * 16;
    const uint32_t bRow = (uint32_t)(l7 + ((lane >> 4) & 1) * 8) * 80 + ((lane >> 3) & 1) * 16;
    const uint32_t vRow = (uint32_t)(lane & 15) * 80 + ((lane >> 4) & 1) * 16;

    const int q0 = w * 32;

#pragma unroll 1
    for (int mi = 0; mi < 2; mi++) {
        float accs[8][4];
#pragma unroll
        for (int ni = 0; ni < 8; ni++)
#pragma unroll
            for (int c = 0; c < 4; c++) accs[ni][c] = 0.f;

        const uint32_t aBase = qsb + (uint32_t)(q0 + mi * 16) * 80 + aRow;
#pragma unroll
        for (int kt = 0; kt < 2; kt++) {
            uint32_t af[4];
            ldsm4(af, aBase + kt * 32);
#pragma unroll
            for (int nip = 0; nip < 4; nip++) {
                uint32_t bf[4];
                ldsm4(bf, ksb + (uint32_t)(nip * 16) * 80 + bRow + kt * 32);
                mma16(accs[2 * nip],     af, bf);
                mma16(accs[2 * nip + 1], af, bf + 2);
            }
        }

        const int r0 = q0 + mi * 16 + g;
        const int r1 = r0 + 8;
        const int i0 = r0 >> 3, j0 = r0 & 7;
        const int i1 = r1 >> 3, j1 = r1 & 7;
        const int l0 = lab[r0], l1 = lab[r1];
        float mx0 = -1e30f, mx1 = -1e30f;
#pragma unroll
        for (int ni = 0; ni < 8; ni++) {
#pragma unroll
            for (int cc = 0; cc < 2; cc++) {
                const int col = 8 * ni + 2 * tig + cc;
                const int i2 = col >> 3, j2 = col & 7;
                const int lc = lab[col];
                float s0 = accs[ni][cc] * 0.17677669529663687f +
                           sbias[(i0 - i2 + 7) * 15 + (j0 - j2 + 7)];
                float s1 = accs[ni][2 + cc] * 0.17677669529663687f +
                           sbias[(i1 - i2 + 7) * 15 + (j1 - j2 + 7)];
                if (lc != l0) s0 -= 100.f;
                if (lc != l1) s1 -= 100.f;
                accs[ni][cc] = s0;
                accs[ni][2 + cc] = s1;
                mx0 = fmaxf(mx0, s0);
                mx1 = fmaxf(mx1, s1);
            }
        }
        mx0 = fmaxf(mx0, __shfl_xor_sync(0xffffffffu, mx0, 1));
        mx0 = fmaxf(mx0, __shfl_xor_sync(0xffffffffu, mx0, 2));
        mx1 = fmaxf(mx1, __shfl_xor_sync(0xffffffffu, mx1, 1));
        mx1 = fmaxf(mx1, __shfl_xor_sync(0xffffffffu, mx1, 2));
        float sum0 = 0.f, sum1 = 0.f;
#pragma unroll
        for (int ni = 0; ni < 8; ni++) {
#pragma unroll
            for (int cc = 0; cc < 2; cc++) {
                const float e0 = __expf(accs[ni][cc] - mx0);
                const float e1 = __expf(accs[ni][2 + cc] - mx1);
                accs[ni][cc] = e0;
                accs[ni][2 + cc] = e1;
                sum0 += e0;
                sum1 += e1;
            }
        }
        sum0 += __shfl_xor_sync(0xffffffffu, sum0, 1);
        sum0 += __shfl_xor_sync(0xffffffffu, sum0, 2);
        sum1 += __shfl_xor_sync(0xffffffffu, sum1, 1);
        sum1 += __shfl_xor_sync(0xffffffffu, sum1, 2);
        const float inv0 = __fdividef(1.f, sum0);
        const float inv1 = __fdividef(1.f, sum1);

        uint32_t pa[4][4];
#pragma unroll
        for (int kt = 0; kt < 4; kt++) {
            __half2 h;
            h = __floats2half2_rn(accs[2 * kt][0] * inv0, accs[2 * kt][1] * inv0);
            pa[kt][0] = *(const uint32_t*)&h;
            h = __floats2half2_rn(accs[2 * kt][2] * inv1, accs[2 * kt][3] * inv1);
            pa[kt][1] = *(const uint32_t*)&h;
            h = __floats2half2_rn(accs[2 * kt + 1][0] * inv0, accs[2 * kt + 1][1] * inv0);
            pa[kt][2] = *(const uint32_t*)&h;
            h = __floats2half2_rn(accs[2 * kt + 1][2] * inv1, accs[2 * kt + 1][3] * inv1);
            pa[kt][3] = *(const uint32_t*)&h;
        }

        float acco[4][4];
#pragma unroll
        for (int nj = 0; nj < 4; nj++)
#pragma unroll
            for (int c = 0; c < 4; c++) acco[nj][c] = 0.f;
#pragma unroll
        for (int kt = 0; kt < 4; kt++) {
#pragma unroll
            for (int njp = 0; njp < 2; njp++) {
                uint32_t vb[4];
                ldsm4t(vb, vsb + (uint32_t)(kt * 16) * 80 + vRow + njp * 32);
                mma16(acco[2 * njp],     pa[kt], vb);
                mma16(acco[2 * njp + 1], pa[kt], vb + 2);
            }
        }

        __half* d0 = out + ((long)win * NPW + r0) * Cdim + head * HD;
        __half* d1 = out + ((long)win * NPW + r1) * Cdim + head * HD;
#pragma unroll
        for (int nj = 0; nj < 4; nj++) {
            const int col = 8 * nj + 2 * tig;
            *(__half2*)(d0 + col) = __floats2half2_rn(acco[nj][0], acco[nj][1]);
            *(__half2*)(d1 + col) = __floats2half2_rn(acco[nj][2], acco[nj][3]);
        }
    }
}

// ---------------------------------------------------------------------------
// Launch
// ---------------------------------------------------------------------------
extern "C" void kernel_launch(void* const* d_in, const int* in_sizes, int n_in,
                              void* d_out, int out_size)
{
    const float* x      = (const float*)d_in[0];
    const float* g1     = (const float*)d_in[1];
    const float* b1     = (const float*)d_in[2];
    const float* qkv_w  = (const float*)d_in[3];
    const float* qkv_b  = (const float*)d_in[4];
    const float* rpb    = (const float*)d_in[5];
    const float* proj_w = (const float*)d_in[6];
    const float* proj_b = (const float*)d_in[7];
    const float* g2     = (const float*)d_in[8];
    const float* b2     = (const float*)d_in[9];
    const float* fc1_w  = (const float*)d_in[10];
    const float* fc1_b  = (const float*)d_in[11];
    const float* fc2_w  = (const float*)d_in[12];
    const float* fc2_b  = (const float*)d_in[13];
    float* out = (float*)d_out;

    __half *p_qkv, *p_att, *p_ln2, *p_hh, *p_wh;
    float *p_x1;
    cudaGetSymbolAddress((void**)&p_qkv, g_qkv);
    cudaGetSymbolAddress((void**)&p_att, g_att);
    cudaGetSymbolAddress((void**)&p_ln2, g_ln2);
    cudaGetSymbolAddress((void**)&p_hh,  g_hh);
    cudaGetSymbolAddress((void**)&p_x1,  g_x1);
    cudaGetSymbolAddress((void**)&p_wh,  g_wh);

    static bool attr_set = false;
    if (!attr_set) {
        cudaFuncSetAttribute(gemm_ln,   cudaFuncAttributeMaxDynamicSharedMemorySize, LN_SMEM);
        cudaFuncSetAttribute(gemm_ha,   cudaFuncAttributeMaxDynamicSharedMemorySize, HA_SMEM);
        cudaFuncSetAttribute(gemm_h<3>, cudaFuncAttributeMaxDynamicSharedMemorySize, GEMM_SMEM);
        cudaFuncSetAttribute(gemm_h<2>, cudaFuncAttributeMaxDynamicSharedMemorySize, GEMM_SMEM);
        attr_set = true;
    }

    __half* w_qkv = p_wh;
    __half* w_prj = p_wh + 110592;
    __half* w_fc1 = p_wh + 147456;
    __half* w_fc2 = p_wh + 294912;

    // 0. weights fp32 -> fp16
    tohalf_all<<<442368 / 1024, 256>>>(qkv_w, proj_w, fc1_w, fc2_w, p_wh);

    const int M = NTOK;  // 131072, 2048 M-tiles of 64

    // 1. QKV (fused LN1 + shift/window gather)
    gemm_ln<<<M / 64, NTH, LN_SMEM>>>(x, w_qkv, qkv_b, g1, b1, p_qkv, 3 * Cdim);

    // 2. Window attention (mma.sync)
    attn_kernel<<<dim3(NWIN, NH), 64>>>(p_qkv, rpb, p_att);

    // 3. proj + unshift + x residual -> x1 fp32; fused LN2 -> ln2 fp16
    gemm_h<3><<<M / 64, NTH, GEMM_SMEM>>>(
        p_att, w_prj, proj_b, x, p_x1, p_ln2, g2, b2, Cdim, Cdim);

    // 4. FC1 + GELU (A-resident)
    gemm_ha<<<M / 64, NTH, HA_SMEM>>>(p_ln2, w_fc1, fc1_b, p_hh, HID);

    // 5. FC2 + x1 residual -> out fp32
    gemm_h<2><<<M / 64, NTH, GEMM_SMEM>>>(
        p_hh, w_fc2, fc2_b, p_x1, out, nullptr, nullptr, nullptr, Cdim, HID);
}